// round 6
// baseline (speedup 1.0000x reference)
#include <cuda_runtime.h>
#include <stdint.h>

// KVGather (dedup formulation):
//   out[n, d, w, c] = r_weight[n, d] * kv[n, r_idx[n, d], w, c],  d = i*TOPK+k in [0,512)
// Shapes: N=16, P2=64, TOPK=8, W2=64, C_KV=128.
// Inputs: r_idx int32 (N,P2,TOPK), r_weight f32 (N,P2,TOPK), kv f32 (N,P2,W2,C_KV).
// Output f32 256 MB.
//
// R6: RETRY of R5 (broker-level container failure; kernel never ran).
// Inverted gather: one CTA per (n, src, slice): scan the 512 routing entries
// of batch n for matches to src, load the kv slice ONCE into registers, fan
// out scaled copies to all matching destinations. Cuts L2 read traffic 8x
// (256MB -> 32MB) and removes ~all LDG wavefronts from L1tex, freeing the
// L1/L2 path for the irreducible 256MB write stream.

static constexpr int N      = 16;
static constexpr int P2     = 64;
static constexpr int TOPK   = 8;
static constexpr int DPB    = P2 * TOPK;     // 512 destinations per batch
static constexpr int WC4    = 64 * 128 / 4;  // 2048 float4 per block (32 KB)
static constexpr int SLICES = 4;             // 512 float4 (8 KB) per slice
static constexpr int SL4    = WC4 / SLICES;  // 512
static constexpr int THREADS = 256;          // 2 float4 per thread per slice

__global__ __launch_bounds__(THREADS)
void kv_gather_dedup_kernel(const int*    __restrict__ r_idx,
                            const float*  __restrict__ r_weight,
                            const float4* __restrict__ kv4,
                            float4*       __restrict__ out4) {
    __shared__ int   s_cnt;
    __shared__ short s_dst[DPB];
    __shared__ float s_wt[DPB];

    const int b     = blockIdx.x;                    // 0 .. N*P2*SLICES-1 (4096)
    const int slice = b & (SLICES - 1);
    const int src   = (b >> 2) & (P2 - 1);
    const int n     = b >> 8;                        // / (P2*SLICES)
    const int tid   = threadIdx.x;

    if (tid == 0) s_cnt = 0;
    __syncthreads();

    // Phase 1: scan routing table of batch n for destinations matching src.
    for (int e = tid; e < DPB; e += THREADS) {
        const int gi = n * DPB + e;
        if ((r_idx[gi] & (P2 - 1)) == src) {
            const int pos = atomicAdd(&s_cnt, 1);
            s_dst[pos] = (short)e;
            s_wt[pos]  = r_weight[gi];
        }
    }
    __syncthreads();

    const int cnt = s_cnt;
    if (cnt == 0) return;

    // Phase 2: load this kv slice once (registers).
    const float4* __restrict__ s =
        kv4 + (long long)(n * P2 + src) * WC4 + slice * SL4;
    const float4 v0 = __ldg(s + tid);
    const float4 v1 = __ldg(s + tid + THREADS);

    // Phase 3: fan out scaled copies to every matching destination.
    float4* const out_n = out4 + (long long)n * DPB * WC4 + slice * SL4;
    for (int j = 0; j < cnt; ++j) {
        const int   d  = s_dst[j];
        const float wt = s_wt[j];
        float4* __restrict__ dp = out_n + (long long)d * WC4;
        float4 a, c;
        a.x = v0.x * wt; a.y = v0.y * wt; a.z = v0.z * wt; a.w = v0.w * wt;
        c.x = v1.x * wt; c.y = v1.y * wt; c.z = v1.z * wt; c.w = v1.w * wt;
        __stcs(dp + tid,           a);
        __stcs(dp + tid + THREADS, c);
    }
}

extern "C" void kernel_launch(void* const* d_in, const int* in_sizes, int n_in,
                              void* d_out, int out_size) {
    const int*    r_idx    = (const int*)d_in[0];
    const float*  r_weight = (const float*)d_in[1];
    const float4* kv4      = (const float4*)d_in[2];
    float4*       out4     = (float4*)d_out;

    kv_gather_dedup_kernel<<<N * P2 * SLICES, THREADS>>>(r_idx, r_weight, kv4, out4);
}

// round 8
// speedup vs baseline: 1.0006x; 1.0006x over previous
#include <cuda_runtime.h>
#include <stdint.h>

// KVGather: out[n, i, k, w, c] = r_weight[n,i,k] * kv[n, r_idx[n,i,k], w, c]
// N=16, P2=64, TOPK=8, W2=64, C_KV=128. idx int32, weight f32, kv f32. Out 256 MB f32.
//
// R8: RETRY of R7 (broker-level container failure; kernel never ran).
// Writes go through TMA bulk stores (cp.async.bulk shared->global) instead of
// STG.128, removing ~16.8M STG issue slots + their L1tex wavefronts. Loads remain
// LDG (L2-resident kv). Double-buffered 8KB SMEM staging per CTA.

static constexpr int N       = 16;
static constexpr int P2      = 64;
static constexpr int TOPK    = 8;
static constexpr int WC4     = 64 * 128 / 4;   // 2048 float4 per gathered block (32 KB)
static constexpr int SLICES  = 4;
static constexpr int SL4     = WC4 / SLICES;   // 512 float4 = 8 KB per slice
static constexpr int THREADS = 256;            // 2 float4 per thread per slice
static constexpr int SLICE_BYTES = SL4 * 16;   // 8192

__global__ __launch_bounds__(THREADS)
void kv_gather_tma_kernel(const int*    __restrict__ r_idx,
                          const float*  __restrict__ r_weight,
                          const float4* __restrict__ kv4,
                          float4*       __restrict__ out4) {
    __shared__ alignas(128) float4 buf[2][SL4];

    const int g   = blockIdx.x;                 // 0 .. 8191 (one CTA per destination block)
    const int n   = g >> 9;                     // / (P2*TOPK)
    const int tid = threadIdx.x;

    const int   src = r_idx[g] & (P2 - 1);
    const float wt  = r_weight[g];

    const float4* __restrict__ s = kv4  + (long long)(n * P2 + src) * WC4;
    float4*       __restrict__ d = out4 + (long long)g * WC4;

    #pragma unroll
    for (int sl = 0; sl < SLICES; ++sl) {
        const int pb = sl & 1;

        // Before reusing a buffer, make sure its previous bulk-store has read it out.
        if (sl >= 2) {
            if (tid == 0)
                asm volatile("cp.async.bulk.wait_group.read 1;" ::: "memory");
            __syncthreads();
        }

        // Load slice from kv (L2-resident), scale, stage in SMEM.
        const float4* sp = s + sl * SL4;
        float4 v0 = __ldg(sp + tid);
        float4 v1 = __ldg(sp + tid + THREADS);
        v0.x *= wt; v0.y *= wt; v0.z *= wt; v0.w *= wt;
        v1.x *= wt; v1.y *= wt; v1.z *= wt; v1.w *= wt;
        buf[pb][tid]           = v0;
        buf[pb][tid + THREADS] = v1;

        // Order generic-proxy STS before the async-proxy bulk read.
        asm volatile("fence.proxy.async.shared::cta;" ::: "memory");
        __syncthreads();

        if (tid == 0) {
            uint32_t smem_addr = (uint32_t)__cvta_generic_to_shared(&buf[pb][0]);
            asm volatile(
                "cp.async.bulk.global.shared::cta.bulk_group [%0], [%1], %2;"
                :: "l"(d + sl * SL4), "r"(smem_addr), "n"(SLICE_BYTES)
                : "memory");
            asm volatile("cp.async.bulk.commit_group;" ::: "memory");
        }
    }

    // Drain all outstanding bulk stores before exit.
    if (tid == 0)
        asm volatile("cp.async.bulk.wait_group 0;" ::: "memory");
}

extern "C" void kernel_launch(void* const* d_in, const int* in_sizes, int n_in,
                              void* d_out, int out_size) {
    const int*    r_idx    = (const int*)d_in[0];
    const float*  r_weight = (const float*)d_in[1];
    const float4* kv4      = (const float4*)d_in[2];
    float4*       out4     = (float4*)d_out;

    kv_gather_tma_kernel<<<N * P2 * TOPK, THREADS>>>(r_idx, r_weight, kv4, out4);
}

// round 9
// speedup vs baseline: 1.0131x; 1.0125x over previous
#include <cuda_runtime.h>
#include <stdint.h>

// KVGather: out[n, i, k, w, c] = r_weight[n,i,k] * kv[n, r_idx[n,i,k], w, c]
// N=16, P2=64, TOPK=8, W2=64, C_KV=128. idx int32, weight f32, kv f32. Out 256 MB f32.
//
// R8: RETRY of R7 (broker-level container failure; kernel never ran).
// Writes go through TMA bulk stores (cp.async.bulk shared->global) instead of
// STG.128, removing ~16.8M STG issue slots + their L1tex wavefronts. Loads remain
// LDG (L2-resident kv). Double-buffered 8KB SMEM staging per CTA.

static constexpr int N       = 16;
static constexpr int P2      = 64;
static constexpr int TOPK    = 8;
static constexpr int WC4     = 64 * 128 / 4;   // 2048 float4 per gathered block (32 KB)
static constexpr int SLICES  = 4;
static constexpr int SL4     = WC4 / SLICES;   // 512 float4 = 8 KB per slice
static constexpr int THREADS = 256;            // 2 float4 per thread per slice
static constexpr int SLICE_BYTES = SL4 * 16;   // 8192

__global__ __launch_bounds__(THREADS)
void kv_gather_tma_kernel(const int*    __restrict__ r_idx,
                          const float*  __restrict__ r_weight,
                          const float4* __restrict__ kv4,
                          float4*       __restrict__ out4) {
    __shared__ alignas(128) float4 buf[2][SL4];

    const int g   = blockIdx.x;                 // 0 .. 8191 (one CTA per destination block)
    const int n   = g >> 9;                     // / (P2*TOPK)
    const int tid = threadIdx.x;

    const int   src = r_idx[g] & (P2 - 1);
    const float wt  = r_weight[g];

    const float4* __restrict__ s = kv4  + (long long)(n * P2 + src) * WC4;
    float4*       __restrict__ d = out4 + (long long)g * WC4;

    #pragma unroll
    for (int sl = 0; sl < SLICES; ++sl) {
        const int pb = sl & 1;

        // Before reusing a buffer, make sure its previous bulk-store has read it out.
        if (sl >= 2) {
            if (tid == 0)
                asm volatile("cp.async.bulk.wait_group.read 1;" ::: "memory");
            __syncthreads();
        }

        // Load slice from kv (L2-resident), scale, stage in SMEM.
        const float4* sp = s + sl * SL4;
        float4 v0 = __ldg(sp + tid);
        float4 v1 = __ldg(sp + tid + THREADS);
        v0.x *= wt; v0.y *= wt; v0.z *= wt; v0.w *= wt;
        v1.x *= wt; v1.y *= wt; v1.z *= wt; v1.w *= wt;
        buf[pb][tid]           = v0;
        buf[pb][tid + THREADS] = v1;

        // Order generic-proxy STS before the async-proxy bulk read.
        asm volatile("fence.proxy.async.shared::cta;" ::: "memory");
        __syncthreads();

        if (tid == 0) {
            uint32_t smem_addr = (uint32_t)__cvta_generic_to_shared(&buf[pb][0]);
            asm volatile(
                "cp.async.bulk.global.shared::cta.bulk_group [%0], [%1], %2;"
                :: "l"(d + sl * SL4), "r"(smem_addr), "n"(SLICE_BYTES)
                : "memory");
            asm volatile("cp.async.bulk.commit_group;" ::: "memory");
        }
    }

    // Drain all outstanding bulk stores before exit.
    if (tid == 0)
        asm volatile("cp.async.bulk.wait_group 0;" ::: "memory");
}

extern "C" void kernel_launch(void* const* d_in, const int* in_sizes, int n_in,
                              void* d_out, int out_size) {
    const int*    r_idx    = (const int*)d_in[0];
    const float*  r_weight = (const float*)d_in[1];
    const float4* kv4      = (const float4*)d_in[2];
    float4*       out4     = (float4*)d_out;

    kv_gather_tma_kernel<<<N * P2 * TOPK, THREADS>>>(r_idx, r_weight, kv4, out4);
}